// round 1
// baseline (speedup 1.0000x reference)
#include <cuda_runtime.h>
#include <math.h>

#define BB 32
#define MM 60
#define NN 8400
#define CC 80
#define INF_COST 1e8f

// Scratch (device globals: allocation-free)
__device__ float g_cost[(size_t)BB * MM * NN];               // [b][m][n]
__device__ float g_iou [(size_t)BB * MM * NN];               // [b][m][n]
__device__ unsigned long long g_mask[(size_t)BB * NN];       // per-prior GT bitmask
__device__ unsigned char g_valid[(size_t)BB * NN];

__device__ __forceinline__ unsigned int f2o(float f) {
    unsigned int u = __float_as_uint(f);
    return (u & 0x80000000u) ? ~u : (u | 0x80000000u);  // monotonic float->uint
}

// Pass A0: valid_mask per (b, n); also zero matching masks.
__global__ void k_valid(const float* __restrict__ priors,
                        const float* __restrict__ gt_bboxes,
                        const float* __restrict__ pad_flag) {
    int idx = blockIdx.x * blockDim.x + threadIdx.x;
    if (idx >= BB * NN) return;
    int b = idx / NN, n = idx % NN;
    float px = priors[n * 4 + 0], py = priors[n * 4 + 1];
    const float* gb = gt_bboxes + (size_t)b * MM * 4;
    const float* pf = pad_flag + (size_t)b * MM;
    bool any = false;
    for (int m = 0; m < MM; m++) {
        float x1 = gb[m * 4 + 0], y1 = gb[m * 4 + 1];
        float x2 = gb[m * 4 + 2], y2 = gb[m * 4 + 3];
        float mn = fminf(fminf(px - x1, py - y1), fminf(x2 - px, y2 - py));
        if (mn > 0.f && pf[m] > 0.f) any = true;
    }
    g_valid[idx] = any ? 1 : 0;
    g_mask[idx] = 0ull;
}

// Pass A1: cost + iou, stored transposed [b][m][n].
__global__ void k_cost(const float* __restrict__ pred_bboxes,
                       const float* __restrict__ pred_scores,
                       const float* __restrict__ priors,
                       const int* __restrict__ gt_labels,
                       const float* __restrict__ gt_bboxes) {
    int n = blockIdx.x * blockDim.x + threadIdx.x;
    if (n >= NN) return;
    int bm = blockIdx.y;
    int b = bm / MM, m = bm % MM;

    const float* gb = gt_bboxes + ((size_t)b * MM + m) * 4;
    float gx1 = gb[0], gy1 = gb[1], gx2 = gb[2], gy2 = gb[3];
    int label = gt_labels[b * MM + m];

    float px = priors[n * 4 + 0], py = priors[n * 4 + 1];
    float stride = priors[n * 4 + 2];

    float4 pb = ((const float4*)pred_bboxes)[(size_t)b * NN + n];

    // pairwise IoU
    float lx = fmaxf(pb.x, gx1), ly = fmaxf(pb.y, gy1);
    float rx = fminf(pb.z, gx2), ry = fminf(pb.w, gy2);
    float iw = fmaxf(rx - lx, 0.f), ih = fmaxf(ry - ly, 0.f);
    float inter = iw * ih;
    float a1 = (pb.z - pb.x) * (pb.w - pb.y);
    float a2 = (gx2 - gx1) * (gy2 - gy1);
    float uni = fmaxf(a1 + a2 - inter, 1e-6f);
    float iou = inter / uni;

    size_t o = ((size_t)bm) * NN + n;
    g_iou[o] = iou;

    float cost;
    if (!g_valid[b * NN + n]) {
        cost = INF_COST;
    } else {
        float cx = 0.5f * (gx1 + gx2), cy = 0.5f * (gy1 + gy2);
        float dx = px - cx, dy = py - cy;
        float dist = sqrtf(dx * dx + dy * dy) / stride;
        float soft = exp10f(dist - 3.0f);
        float iou_cost = -logf(iou + 1e-7f) * 3.0f;
        float t = pred_scores[((size_t)b * NN + n) * CC + label];
        float e = expf(-fabsf(t));
        float sig = (t >= 0.f) ? 1.f / (1.f + e) : e / (1.f + e);
        float bce = fmaxf(t, 0.f) - t * iou + log1pf(e);
        float sc = iou - sig;
        cost = bce * sc * sc + iou_cost + soft;
    }
    g_cost[o] = cost;
}

// Pass B: per (b, m) valid GT: dynamic_ks = max(int(sum top-13 iou), 1),
// then stable-select ks smallest costs -> set bit m in per-prior masks.
__global__ void k_match(const float* __restrict__ pad_flag) {
    int bm = blockIdx.x;
    int b = bm / MM, m = bm % MM;
    if (pad_flag[b * MM + m] <= 0.f) return;

    extern __shared__ float sh[];
    float* s_cost = sh;
    float* s_iou = sh + NN;
    __shared__ unsigned long long s_red[256];

    const float* colc = g_cost + (size_t)bm * NN;
    const float* coli = g_iou + (size_t)bm * NN;
    int tid = threadIdx.x;
    for (int n = tid; n < NN; n += 256) { s_cost[n] = colc[n]; s_iou[n] = coli[n]; }
    __syncthreads();

    // top-13 iou (descending, key = ordered(iou)<<32 | n)
    unsigned long long prev = 0xFFFFFFFFFFFFFFFFull;
    float sum = 0.f;
    for (int it = 0; it < 13; it++) {
        unsigned long long best = 0ull;
        for (int n = tid; n < NN; n += 256) {
            unsigned long long key = ((unsigned long long)f2o(s_iou[n]) << 32) | (unsigned)n;
            if (key < prev && key > best) best = key;
        }
        s_red[tid] = best;
        __syncthreads();
        for (int s = 128; s > 0; s >>= 1) {
            if (tid < s && s_red[tid + s] > s_red[tid]) s_red[tid] = s_red[tid + s];
            __syncthreads();
        }
        prev = s_red[0];
        sum += s_iou[(unsigned)(prev & 0xFFFFFFFFu)];
        __syncthreads();
    }
    int ks = (int)sum;           // truncation toward zero, matches astype(int32)
    if (ks < 1) ks = 1;

    // ks smallest costs (ascending, stable: low index wins ties)
    prev = 0ull;                 // all keys > 0 since cost > 0
    for (int it = 0; it < ks; it++) {
        unsigned long long best = 0xFFFFFFFFFFFFFFFFull;
        for (int n = tid; n < NN; n += 256) {
            unsigned long long key = ((unsigned long long)f2o(s_cost[n]) << 32) | (unsigned)n;
            if (key > prev && key < best) best = key;
        }
        s_red[tid] = best;
        __syncthreads();
        for (int s = 128; s > 0; s >>= 1) {
            if (tid < s && s_red[tid + s] < s_red[tid]) s_red[tid] = s_red[tid + s];
            __syncthreads();
        }
        prev = s_red[0];
        __syncthreads();
        if (tid == 0)
            atomicOr(&g_mask[(size_t)b * NN + (unsigned)(prev & 0xFFFFFFFFu)], 1ull << m);
    }
}

// Pass C: per (b, n) resolve multi-matches, emit all 4 outputs (float32 concat).
__global__ void k_out(const int* __restrict__ gt_labels,
                      const float* __restrict__ gt_bboxes,
                      float* __restrict__ out) {
    int idx = blockIdx.x * blockDim.x + threadIdx.x;
    if (idx >= BB * NN) return;
    int b = idx / NN, n = idx % NN;

    unsigned long long mask = g_mask[idx];
    if (__popcll(mask) > 1) {
        // argmin over ALL m (incl. padded GTs), first-min tie-break — matches jnp.argmin
        unsigned int bo = 0xFFFFFFFFu;
        int am = 0;
        for (int m = 0; m < MM; m++) {
            unsigned int o = f2o(g_cost[((size_t)b * MM + m) * NN + n]);
            if (o < bo) { bo = o; am = m; }
        }
        mask = 1ull << am;
    }
    bool fg = (mask != 0ull);
    int matched = fg ? (__ffsll((long long)mask) - 1) : 0;

    float lab = fg ? (float)gt_labels[b * MM + matched] : (float)CC;
    float metric = fg ? g_iou[((size_t)b * MM + matched) * NN + n] : 0.f;
    float4 bb = make_float4(0.f, 0.f, 0.f, 0.f);
    if (fg) bb = ((const float4*)gt_bboxes)[b * MM + matched];

    size_t S = (size_t)BB * NN;
    out[idx] = lab;                       // assigned_labels
    out[S + idx] = 1.0f;                  // assigned_labels_weights
    ((float4*)(out + 2 * S))[idx] = bb;   // assigned_bboxes
    out[6 * S + idx] = metric;            // assign_metrics
}

extern "C" void kernel_launch(void* const* d_in, const int* in_sizes, int n_in,
                              void* d_out, int out_size) {
    const float* pred_bboxes = (const float*)d_in[0];
    const float* pred_scores = (const float*)d_in[1];
    const float* priors      = (const float*)d_in[2];
    const int*   gt_labels   = (const int*)d_in[3];
    const float* gt_bboxes   = (const float*)d_in[4];
    const float* pad_flag    = (const float*)d_in[5];
    float* out = (float*)d_out;

    k_valid<<<(BB * NN + 255) / 256, 256>>>(priors, gt_bboxes, pad_flag);

    dim3 gc((NN + 255) / 256, BB * MM);
    k_cost<<<gc, 256>>>(pred_bboxes, pred_scores, priors, gt_labels, gt_bboxes);

    size_t shbytes = 2 * (size_t)NN * sizeof(float);  // 67200 B
    cudaFuncSetAttribute(k_match, cudaFuncAttributeMaxDynamicSharedMemorySize, (int)shbytes);
    k_match<<<BB * MM, 256, shbytes>>>(pad_flag);

    k_out<<<(BB * NN + 255) / 256, 256>>>(gt_labels, gt_bboxes, out);
}